// round 15
// baseline (speedup 1.0000x reference)
#include <cuda_runtime.h>
#include <cstdint>

#define MUL 64
#define NODE_TILE 64
#define THREADS 256
#define GRID_CTAS 148

#define ALPHA_C   0.08838834764831845f   /* 1/sqrt(128) */
#define C110_C    0.5773502691896258f    /* 1/sqrt(3) */
#define C011_C    0.5773502691896258f
#define C101_C    0.5773502691896258f

// smem layout (floats)
#define S1 132            // result stride, phase 1 (64 x 132)
#define S2 68             // result stride, phase 2 (256 x 68)
#define OFF_A1   0
#define SZ_A1    8448     // max(64*132 = 8448, frag 4*16*32*4 = 8192)
#define OFF_A2   (OFF_A1 + SZ_A1)
#define SZ_A2    17408    // max(256*68 = 17408, frag 16*8*32*4 = 16384)
#define OFF_ATTR (OFF_A2 + SZ_A2)
#define SMEM_FLOATS (OFF_ATTR + 64*4)
#define SMEM_BYTES  (SMEM_FLOATS * 4)

__device__ __forceinline__ uint32_t tf32_bits(float x) {
    uint32_t u;
    asm("cvt.rna.tf32.f32 %0, %1;" : "=r"(u) : "f"(x));
    return u;
}
__device__ __forceinline__ float to_tf32(float x) {
    return __uint_as_float(tf32_bits(x));
}

__device__ __forceinline__ void mma_tf32(float c[4],
                                         uint32_t a0, uint32_t a1, uint32_t a2, uint32_t a3,
                                         uint32_t b0, uint32_t b1) {
    asm volatile(
        "mma.sync.aligned.m16n8k8.row.col.f32.tf32.tf32.f32 "
        "{%0,%1,%2,%3}, {%4,%5,%6,%7}, {%8,%9}, {%0,%1,%2,%3};"
        : "+f"(c[0]), "+f"(c[1]), "+f"(c[2]), "+f"(c[3])
        : "r"(a0), "r"(a1), "r"(a2), "r"(a3), "r"(b0), "r"(b1));
}

// fragment-major index: value for logical (row, col) of an A operand.
// lane = 4*g + tig holds a0=(g,tig) a1=(g+8,tig) a2=(g,tig+4) a3=(g+8,tig+4)
// phase1: 4 m-frags (64 rows), 16 k-steps; phase2: 16 m-frags (256 rows), 8 k-steps
__device__ __forceinline__ int frag1_idx(int r, int c) {
    int mf = r >> 4, g = r & 7, hi = (r >> 3) & 1;
    int ks = c >> 3, tig = c & 3, half = (c >> 2) & 1;
    return ((mf * 16 + ks) << 7) + (((g << 2) + tig) << 2) + hi + (half << 1);
}
__device__ __forceinline__ int frag2_idx(int r, int c) {
    int mf = r >> 4, g = r & 7, hi = (r >> 3) & 1;
    int ks = c >> 3, tig = c & 3, half = (c >> 2) & 1;
    return ((mf * 8 + ks) << 7) + (((g << 2) + tig) << 2) + hi + (half << 1);
}

__global__ void __launch_bounds__(THREADS, 1)
embedding_kernel(const float* __restrict__ feats,
                 const float* __restrict__ attrs,
                 const float* __restrict__ W1,
                 const float* __restrict__ W2,
                 const float* __restrict__ W3,
                 const float* __restrict__ W4,
                 float* __restrict__ out,
                 int n, int ntiles)
{
    extern __shared__ float sm[];
    float* sA1 = sm + OFF_A1;   // phase1 A frags -> phase1 result [64][S1]
    float* sA2 = sm + OFF_A2;   // phase2 A frags -> phase2 result [256][S2]
    float* sAttr = sm + OFF_ATTR;

    const int tid = threadIdx.x;
    const int lane = tid & 31;
    const int warp = tid >> 5;
    const int g = lane >> 2;       // 0..7
    const int tig = lane & 3;      // 0..3

    // ---------- one-time: preload weight fragments into registers ----------
    uint32_t B1c[16][4][2];        // phase1 warps (0-3): cols [32*warp, +32)
    uint32_t W3c[8][2][2];         // phase2 warps (4-7): cols [16*(warp-4), +16)
    uint32_t W4c[8][2][2];

    if (warp < 4) {
        const int n0 = warp * 32;
        #pragma unroll
        for (int ks = 0; ks < 16; ks++) {
            #pragma unroll
            for (int nt = 0; nt < 4; nt++) {
                const int col = n0 + nt * 8 + g;
                const int ka = ks * 8 + tig;         // ks<8 -> W1 rows, else W2
                float va, vb;
                if (ks < 8) {
                    va = W1[ka * 128 + col];
                    vb = W1[(ka + 4) * 128 + col];
                } else {
                    va = W2[(ka - 64) * 128 + col];
                    vb = W2[(ka - 60) * 128 + col];
                }
                B1c[ks][nt][0] = tf32_bits(va);
                B1c[ks][nt][1] = tf32_bits(vb);
            }
        }
    } else {
        const int n0 = (warp - 4) * 16;
        #pragma unroll
        for (int ks = 0; ks < 8; ks++) {
            #pragma unroll
            for (int nt = 0; nt < 2; nt++) {
                const int col = n0 + nt * 8 + g;
                const int k = ks * 8 + tig;
                W3c[ks][nt][0] = tf32_bits(W3[k * 64 + col]);
                W3c[ks][nt][1] = tf32_bits(W3[(k + 4) * 64 + col]);
                W4c[ks][nt][0] = tf32_bits(W4[k * 64 + col]);
                W4c[ks][nt][1] = tf32_bits(W4[(k + 4) * 64 + col]);
            }
        }
    }

    // ---------- persistent tile loop ----------
    for (int tile = blockIdx.x; tile < ntiles; tile += gridDim.x) {
        const int nb = tile * NODE_TILE;

        __syncthreads();   // previous epilogue done; safe to restage

        // ---- stage node data into fragment-major A buffers ----
        {
            const int z = tid >> 2;        // node 0..63
            const int q = tid & 3;         // quarter of u-range
            const int zg = nb + z;
            const bool valid = (zg < n);

            float4 at4 = valid ? ((const float4*)attrs)[zg] : make_float4(0.f,0.f,0.f,0.f);
            if (q == 0) ((float4*)sAttr)[z] = at4;
            const float a0v = at4.x, a1x = at4.y, a1y = at4.z, a1z = at4.w;

            const float* fr = feats + (size_t)zg * (4 * MUL);

            // x0 quarter: cols u in [16q, 16q+16)
            #pragma unroll
            for (int j = 0; j < 4; j++) {
                float4 f = valid ? ((const float4*)fr)[q * 4 + j] : make_float4(0.f,0.f,0.f,0.f);
                float vv[4] = {f.x, f.y, f.z, f.w};
                #pragma unroll
                for (int i = 0; i < 4; i++) {
                    const int u = q * 16 + j * 4 + i;
                    sA2[frag2_idx(z, u)] = to_tf32(vv[i]);          // X0 rows 0-63
                    sA1[frag1_idx(z, u)] = to_tf32(a0v * vv[i]);    // a0*x0
                }
            }

            // x1 quarter: 48 floats
            float vb[48];
            #pragma unroll
            for (int j = 0; j < 12; j++) {
                float4 f = valid ? ((const float4*)(fr + 64))[q * 12 + j]
                                 : make_float4(0.f,0.f,0.f,0.f);
                vb[4*j+0] = f.x; vb[4*j+1] = f.y; vb[4*j+2] = f.z; vb[4*j+3] = f.w;
            }
            #pragma unroll
            for (int uu = 0; uu < 16; uu++) {
                const int u = q * 16 + uu;
                const float c0 = vb[3*uu], c1 = vb[3*uu+1], c2 = vb[3*uu+2];
                sA1[frag1_idx(z, 64 + u)] =
                    to_tf32(C110_C * (a1x * c0 + a1y * c1 + a1z * c2));
                sA2[frag2_idx(64 + z, u)]  = to_tf32(c0);
                sA2[frag2_idx(128 + z, u)] = to_tf32(c1);
                sA2[frag2_idx(192 + z, u)] = to_tf32(c2);
            }
        }
        __syncthreads();

        if (warp < 4) {
            // ---- phase 1: SG(64x128) = A1 @ [W1;W2], warp owns cols [32w,+32) ----
            const int n0 = warp * 32;
            float acc[4][4][4];
            #pragma unroll
            for (int mf = 0; mf < 4; mf++)
                #pragma unroll
                for (int nt = 0; nt < 4; nt++)
                    #pragma unroll
                    for (int i = 0; i < 4; i++) acc[mf][nt][i] = 0.f;

            #pragma unroll
            for (int ks = 0; ks < 16; ks++) {
                #pragma unroll
                for (int mf = 0; mf < 4; mf++) {
                    float4 a = *(const float4*)(sA1 + ((mf * 16 + ks) << 7) + (lane << 2));
                    const uint32_t a0 = __float_as_uint(a.x);
                    const uint32_t a1 = __float_as_uint(a.y);
                    const uint32_t a2 = __float_as_uint(a.z);
                    const uint32_t a3 = __float_as_uint(a.w);
                    #pragma unroll
                    for (int nt = 0; nt < 4; nt++)
                        mma_tf32(acc[mf][nt], a0, a1, a2, a3,
                                 B1c[ks][nt][0], B1c[ks][nt][1]);
                }
            }
            asm volatile("bar.sync 1, 128;" ::: "memory");   // group reads done
            #pragma unroll
            for (int mf = 0; mf < 4; mf++) {
                const int r0 = mf * 16 + g;
                #pragma unroll
                for (int nt = 0; nt < 4; nt++) {
                    const int col = n0 + nt * 8 + 2 * tig;
                    *(float2*)(sA1 + r0 * S1 + col)       = make_float2(acc[mf][nt][0], acc[mf][nt][1]);
                    *(float2*)(sA1 + (r0 + 8) * S1 + col) = make_float2(acc[mf][nt][2], acc[mf][nt][3]);
                }
            }
        } else {
            // ---- phase 2: [V;Z](256x64) = [X0;X1c] @ (W3|W4), warp owns cols [16(w-4),+16) ----
            const int n0 = (warp - 4) * 16;
            float acc[16][2][4];
            #pragma unroll
            for (int mf = 0; mf < 16; mf++)
                #pragma unroll
                for (int nt = 0; nt < 2; nt++)
                    #pragma unroll
                    for (int i = 0; i < 4; i++) acc[mf][nt][i] = 0.f;

            #pragma unroll
            for (int ks = 0; ks < 8; ks++) {
                // rows 0-63 (X0) use W3
                #pragma unroll
                for (int mf = 0; mf < 4; mf++) {
                    float4 a = *(const float4*)(sA2 + ((mf * 8 + ks) << 7) + (lane << 2));
                    const uint32_t a0 = __float_as_uint(a.x);
                    const uint32_t a1 = __float_as_uint(a.y);
                    const uint32_t a2 = __float_as_uint(a.z);
                    const uint32_t a3 = __float_as_uint(a.w);
                    #pragma unroll
                    for (int nt = 0; nt < 2; nt++)
                        mma_tf32(acc[mf][nt], a0, a1, a2, a3,
                                 W3c[ks][nt][0], W3c[ks][nt][1]);
                }
                // rows 64-255 (X1 components) use W4
                #pragma unroll
                for (int mf = 4; mf < 16; mf++) {
                    float4 a = *(const float4*)(sA2 + ((mf * 8 + ks) << 7) + (lane << 2));
                    const uint32_t a0 = __float_as_uint(a.x);
                    const uint32_t a1 = __float_as_uint(a.y);
                    const uint32_t a2 = __float_as_uint(a.z);
                    const uint32_t a3 = __float_as_uint(a.w);
                    #pragma unroll
                    for (int nt = 0; nt < 2; nt++)
                        mma_tf32(acc[mf][nt], a0, a1, a2, a3,
                                 W4c[ks][nt][0], W4c[ks][nt][1]);
                }
            }
            asm volatile("bar.sync 2, 128;" ::: "memory");
            #pragma unroll
            for (int mf = 0; mf < 16; mf++) {
                const int r0 = mf * 16 + g;
                #pragma unroll
                for (int nt = 0; nt < 2; nt++) {
                    const int col = n0 + nt * 8 + 2 * tig;
                    *(float2*)(sA2 + r0 * S2 + col)       = make_float2(acc[mf][nt][0], acc[mf][nt][1]);
                    *(float2*)(sA2 + (r0 + 8) * S2 + col) = make_float2(acc[mf][nt][2], acc[mf][nt][3]);
                }
            }
        }
        __syncthreads();   // both phase results visible

        // ---- epilogue: gate + coalesced float4 writes ----
        #pragma unroll
        for (int it = 0; it < 4; it++) {
            const int unit = it * THREADS + tid;      // 0..1023
            const int z = unit >> 4;                  // node
            const int grp = unit & 15;                // group of 4 w's
            const int w4 = grp << 2;
            const int zg = nb + z;
            if (zg >= n) continue;

            float4 s4  = *(const float4*)(sA1 + z * S1 + w4);
            float4 g4  = *(const float4*)(sA1 + z * S1 + 64 + w4);
            float4 v4  = *(const float4*)(sA2 + z * S2 + w4);
            float4 z04 = *(const float4*)(sA2 + (64  + z) * S2 + w4);
            float4 z14 = *(const float4*)(sA2 + (128 + z) * S2 + w4);
            float4 z24 = *(const float4*)(sA2 + (192 + z) * S2 + w4);
            float4 at  = ((const float4*)sAttr)[z];

            float sv[4] = {s4.x, s4.y, s4.z, s4.w};
            float gv[4] = {g4.x, g4.y, g4.z, g4.w};
            float vv[4] = {v4.x, v4.y, v4.z, v4.w};
            float zz0[4] = {z04.x, z04.y, z04.z, z04.w};
            float zz1[4] = {z14.x, z14.y, z14.z, z14.w};
            float zz2[4] = {z24.x, z24.y, z24.z, z24.w};

            float silu4[4], r[12];
            #pragma unroll
            for (int i = 0; i < 4; i++) {
                const float s = ALPHA_C * sv[i];
                const float gg = ALPHA_C * gv[i];
                const float sig = 1.0f / (1.0f + __expf(-gg));
                silu4[i] = s / (1.0f + __expf(-s));
                const float c011v = C011_C * vv[i];
                const float c101a0 = C101_C * at.x;
                r[3*i+0] = sig * ALPHA_C * (c011v * at.y + c101a0 * zz0[i]);
                r[3*i+1] = sig * ALPHA_C * (c011v * at.z + c101a0 * zz1[i]);
                r[3*i+2] = sig * ALPHA_C * (c011v * at.w + c101a0 * zz2[i]);
            }

            float* ob = out + (size_t)zg * (4 * MUL);
            *(float4*)(ob + w4) = make_float4(silu4[0], silu4[1], silu4[2], silu4[3]);
            float* og = ob + 64 + 12 * grp;
            *(float4*)(og + 0) = make_float4(r[0], r[1], r[2],  r[3]);
            *(float4*)(og + 4) = make_float4(r[4], r[5], r[6],  r[7]);
            *(float4*)(og + 8) = make_float4(r[8], r[9], r[10], r[11]);
        }
    }
}

extern "C" void kernel_launch(void* const* d_in, const int* in_sizes, int n_in,
                              void* d_out, int out_size)
{
    const float* feats = (const float*)d_in[0];
    const float* attrs = (const float*)d_in[1];
    const float* W1 = (const float*)d_in[2];
    const float* W2 = (const float*)d_in[3];
    const float* W3 = (const float*)d_in[4];
    const float* W4 = (const float*)d_in[5];
    float* out = (float*)d_out;

    const int n = in_sizes[0] / (4 * MUL);
    const int ntiles = (n + NODE_TILE - 1) / NODE_TILE;

    cudaFuncSetAttribute(embedding_kernel,
                         cudaFuncAttributeMaxDynamicSharedMemorySize, SMEM_BYTES);

    int grid = GRID_CTAS < ntiles ? GRID_CTAS : ntiles;
    embedding_kernel<<<grid, THREADS, SMEM_BYTES>>>(feats, attrs, W1, W2, W3, W4,
                                                    out, n, ntiles);
}

// round 16
// speedup vs baseline: 1.0074x; 1.0074x over previous
#include <cuda_runtime.h>
#include <cstdint>

#define MUL 64
#define NODE_TILE 64
#define THREADS 256
#define GRID_CTAS 152

#define ALPHA_C   0.08838834764831845f   /* 1/sqrt(128) */
#define C110_C    0.5773502691896258f    /* 1/sqrt(3) */
#define C011_C    0.5773502691896258f
#define C101_C    0.5773502691896258f

// smem layout (floats)
#define S1 132            // result stride, phase 1 (64 x 132)
#define S2 68             // result stride, phase 2 (256 x 68)
#define OFF_A1   0
#define SZ_A1    8448     // max(64*132 = 8448, frag 4*16*32*4 = 8192)
#define OFF_A2   (OFF_A1 + SZ_A1)
#define SZ_A2    17408    // max(256*68 = 17408, frag 16*8*32*4 = 16384)
#define OFF_ATTR (OFF_A2 + SZ_A2)
#define SMEM_FLOATS (OFF_ATTR + 64*4)
#define SMEM_BYTES  (SMEM_FLOATS * 4)

__device__ __forceinline__ uint32_t tf32_bits(float x) {
    uint32_t u;
    asm("cvt.rna.tf32.f32 %0, %1;" : "=r"(u) : "f"(x));
    return u;
}
__device__ __forceinline__ float to_tf32(float x) {
    return __uint_as_float(tf32_bits(x));
}

__device__ __forceinline__ void mma_tf32(float c[4],
                                         uint32_t a0, uint32_t a1, uint32_t a2, uint32_t a3,
                                         uint32_t b0, uint32_t b1) {
    asm volatile(
        "mma.sync.aligned.m16n8k8.row.col.f32.tf32.tf32.f32 "
        "{%0,%1,%2,%3}, {%4,%5,%6,%7}, {%8,%9}, {%0,%1,%2,%3};"
        : "+f"(c[0]), "+f"(c[1]), "+f"(c[2]), "+f"(c[3])
        : "r"(a0), "r"(a1), "r"(a2), "r"(a3), "r"(b0), "r"(b1));
}

// fragment-major index: value for logical (row, col) of an A operand.
// lane = 4*g + tig holds a0=(g,tig) a1=(g+8,tig) a2=(g,tig+4) a3=(g+8,tig+4)
// phase1: 4 m-frags (64 rows), 16 k-steps; phase2: 16 m-frags (256 rows), 8 k-steps
__device__ __forceinline__ int frag1_idx(int r, int c) {
    int mf = r >> 4, g = r & 7, hi = (r >> 3) & 1;
    int ks = c >> 3, tig = c & 3, half = (c >> 2) & 1;
    return ((mf * 16 + ks) << 7) + (((g << 2) + tig) << 2) + hi + (half << 1);
}
__device__ __forceinline__ int frag2_idx(int r, int c) {
    int mf = r >> 4, g = r & 7, hi = (r >> 3) & 1;
    int ks = c >> 3, tig = c & 3, half = (c >> 2) & 1;
    return ((mf * 8 + ks) << 7) + (((g << 2) + tig) << 2) + hi + (half << 1);
}

__global__ void __launch_bounds__(THREADS, 1)
embedding_kernel(const float* __restrict__ feats,
                 const float* __restrict__ attrs,
                 const float* __restrict__ W1,
                 const float* __restrict__ W2,
                 const float* __restrict__ W3,
                 const float* __restrict__ W4,
                 float* __restrict__ out,
                 int n, int ntiles)
{
    extern __shared__ float sm[];
    float* sA1 = sm + OFF_A1;   // phase1 A frags -> phase1 result [64][S1]
    float* sA2 = sm + OFF_A2;   // phase2 A frags -> phase2 result [256][S2]
    float* sAttr = sm + OFF_ATTR;

    const int tid = threadIdx.x;
    const int lane = tid & 31;
    const int warp = tid >> 5;
    const int g = lane >> 2;       // 0..7
    const int tig = lane & 3;      // 0..3

    // ---------- one-time: weight fragments in registers (ALL warps, slim) ----------
    // Each warp owns 16 of 128 phase-1 output cols and 8 of 64 phase-2 output cols.
    uint32_t B1c[16][2][2];    // 64 regs
    uint32_t W3c[8][2];        // 16 regs
    uint32_t W4c[8][2];        // 16 regs

    {
        const int n0b = warp * 16;
        #pragma unroll
        for (int ks = 0; ks < 16; ks++) {
            #pragma unroll
            for (int nt = 0; nt < 2; nt++) {
                const int col = n0b + nt * 8 + g;
                const int ka = ks * 8 + tig;     // ks<8 -> W1 rows, else W2
                float va, vb;
                if (ks < 8) {
                    va = W1[ka * 128 + col];
                    vb = W1[(ka + 4) * 128 + col];
                } else {
                    va = W2[(ka - 64) * 128 + col];
                    vb = W2[(ka - 60) * 128 + col];
                }
                B1c[ks][nt][0] = tf32_bits(va);
                B1c[ks][nt][1] = tf32_bits(vb);
            }
        }
        const int colw = warp * 8 + g;
        #pragma unroll
        for (int ks = 0; ks < 8; ks++) {
            const int k = ks * 8 + tig;
            W3c[ks][0] = tf32_bits(W3[k * 64 + colw]);
            W3c[ks][1] = tf32_bits(W3[(k + 4) * 64 + colw]);
            W4c[ks][0] = tf32_bits(W4[k * 64 + colw]);
            W4c[ks][1] = tf32_bits(W4[(k + 4) * 64 + colw]);
        }
    }

    // ---------- persistent tile loop ----------
    for (int tile = blockIdx.x; tile < ntiles; tile += gridDim.x) {
        const int nb = tile * NODE_TILE;

        __syncthreads();   // previous epilogue done; safe to restage

        // ---- stage node data into fragment-major A buffers ----
        {
            const int z = tid >> 2;        // node 0..63
            const int q = tid & 3;         // quarter of u-range
            const int zg = nb + z;
            const bool valid = (zg < n);

            float4 at4 = valid ? ((const float4*)attrs)[zg] : make_float4(0.f,0.f,0.f,0.f);
            if (q == 0) ((float4*)sAttr)[z] = at4;
            const float a0v = at4.x, a1x = at4.y, a1y = at4.z, a1z = at4.w;

            const float* fr = feats + (size_t)zg * (4 * MUL);

            // x0 quarter: cols u in [16q, 16q+16)
            #pragma unroll
            for (int j = 0; j < 4; j++) {
                float4 f = valid ? ((const float4*)fr)[q * 4 + j] : make_float4(0.f,0.f,0.f,0.f);
                float vv[4] = {f.x, f.y, f.z, f.w};
                #pragma unroll
                for (int i = 0; i < 4; i++) {
                    const int u = q * 16 + j * 4 + i;
                    sA2[frag2_idx(z, u)] = to_tf32(vv[i]);          // X0 rows 0-63
                    sA1[frag1_idx(z, u)] = to_tf32(a0v * vv[i]);    // a0*x0
                }
            }

            // x1 quarter: 48 floats
            float vb[48];
            #pragma unroll
            for (int j = 0; j < 12; j++) {
                float4 f = valid ? ((const float4*)(fr + 64))[q * 12 + j]
                                 : make_float4(0.f,0.f,0.f,0.f);
                vb[4*j+0] = f.x; vb[4*j+1] = f.y; vb[4*j+2] = f.z; vb[4*j+3] = f.w;
            }
            #pragma unroll
            for (int uu = 0; uu < 16; uu++) {
                const int u = q * 16 + uu;
                const float c0 = vb[3*uu], c1 = vb[3*uu+1], c2 = vb[3*uu+2];
                sA1[frag1_idx(z, 64 + u)] =
                    to_tf32(C110_C * (a1x * c0 + a1y * c1 + a1z * c2));
                sA2[frag2_idx(64 + z, u)]  = to_tf32(c0);
                sA2[frag2_idx(128 + z, u)] = to_tf32(c1);
                sA2[frag2_idx(192 + z, u)] = to_tf32(c2);
            }
        }
        __syncthreads();

        // ---- phase 1: SG(64x128) = A1 @ [W1;W2]; each warp owns 16 cols ----
        {
            const int n0 = warp * 16;
            float acc[4][2][4];
            #pragma unroll
            for (int mf = 0; mf < 4; mf++)
                #pragma unroll
                for (int nt = 0; nt < 2; nt++)
                    #pragma unroll
                    for (int i = 0; i < 4; i++) acc[mf][nt][i] = 0.f;

            #pragma unroll
            for (int ks = 0; ks < 16; ks++) {
                #pragma unroll
                for (int mf = 0; mf < 4; mf++) {
                    float4 a = *(const float4*)(sA1 + ((mf * 16 + ks) << 7) + (lane << 2));
                    const uint32_t a0 = __float_as_uint(a.x);
                    const uint32_t a1 = __float_as_uint(a.y);
                    const uint32_t a2 = __float_as_uint(a.z);
                    const uint32_t a3 = __float_as_uint(a.w);
                    #pragma unroll
                    for (int nt = 0; nt < 2; nt++)
                        mma_tf32(acc[mf][nt], a0, a1, a2, a3,
                                 B1c[ks][nt][0], B1c[ks][nt][1]);
                }
            }
            __syncthreads();   // all warps done reading sA1 frags
            #pragma unroll
            for (int mf = 0; mf < 4; mf++) {
                const int r0 = mf * 16 + g;
                #pragma unroll
                for (int nt = 0; nt < 2; nt++) {
                    const int col = n0 + nt * 8 + 2 * tig;
                    *(float2*)(sA1 + r0 * S1 + col)       = make_float2(acc[mf][nt][0], acc[mf][nt][1]);
                    *(float2*)(sA1 + (r0 + 8) * S1 + col) = make_float2(acc[mf][nt][2], acc[mf][nt][3]);
                }
            }
        }

        // ---- phase 2: [V;Z](256x64); each warp owns 8 cols; two mf-halves ----
        // Half 1 first (mf 8..15 -> result rows 128..255, smem idx >= 8704) so its
        // stores never touch half-0's frag region (idx 0..8191).
        {
            const int n0 = warp * 8;
            const int colst = n0 + 2 * tig;

            // -- half 1: mf 8..15, all W4 --
            float acc[8][4];
            #pragma unroll
            for (int m = 0; m < 8; m++)
                #pragma unroll
                for (int i = 0; i < 4; i++) acc[m][i] = 0.f;

            #pragma unroll
            for (int ks = 0; ks < 8; ks++) {
                #pragma unroll
                for (int m = 0; m < 8; m++) {
                    const int mf = 8 + m;
                    float4 a = *(const float4*)(sA2 + ((mf * 8 + ks) << 7) + (lane << 2));
                    mma_tf32(acc[m],
                             __float_as_uint(a.x), __float_as_uint(a.y),
                             __float_as_uint(a.z), __float_as_uint(a.w),
                             W4c[ks][0], W4c[ks][1]);
                }
            }
            __syncthreads();   // all warps done reading mf 8..15 frags
            #pragma unroll
            for (int m = 0; m < 8; m++) {
                const int r0 = (8 + m) * 16 + g;
                *(float2*)(sA2 + r0 * S2 + colst)       = make_float2(acc[m][0], acc[m][1]);
                *(float2*)(sA2 + (r0 + 8) * S2 + colst) = make_float2(acc[m][2], acc[m][3]);
            }

            // -- half 0: mf 0..3 use W3, mf 4..7 use W4 --
            #pragma unroll
            for (int m = 0; m < 8; m++)
                #pragma unroll
                for (int i = 0; i < 4; i++) acc[m][i] = 0.f;

            #pragma unroll
            for (int ks = 0; ks < 8; ks++) {
                #pragma unroll
                for (int m = 0; m < 4; m++) {
                    float4 a = *(const float4*)(sA2 + ((m * 8 + ks) << 7) + (lane << 2));
                    mma_tf32(acc[m],
                             __float_as_uint(a.x), __float_as_uint(a.y),
                             __float_as_uint(a.z), __float_as_uint(a.w),
                             W3c[ks][0], W3c[ks][1]);
                }
                #pragma unroll
                for (int m = 4; m < 8; m++) {
                    float4 a = *(const float4*)(sA2 + ((m * 8 + ks) << 7) + (lane << 2));
                    mma_tf32(acc[m],
                             __float_as_uint(a.x), __float_as_uint(a.y),
                             __float_as_uint(a.z), __float_as_uint(a.w),
                             W4c[ks][0], W4c[ks][1]);
                }
            }
            __syncthreads();   // all warps done reading mf 0..7 frags
            #pragma unroll
            for (int m = 0; m < 8; m++) {
                const int r0 = m * 16 + g;
                *(float2*)(sA2 + r0 * S2 + colst)       = make_float2(acc[m][0], acc[m][1]);
                *(float2*)(sA2 + (r0 + 8) * S2 + colst) = make_float2(acc[m][2], acc[m][3]);
            }
        }
        __syncthreads();   // all results visible

        // ---- epilogue: gate + coalesced float4 writes ----
        #pragma unroll
        for (int it = 0; it < 4; it++) {
            const int unit = it * THREADS + tid;      // 0..1023
            const int z = unit >> 4;                  // node
            const int grp = unit & 15;                // group of 4 w's
            const int w4 = grp << 2;
            const int zg = nb + z;
            if (zg >= n) continue;

            float4 s4  = *(const float4*)(sA1 + z * S1 + w4);
            float4 g4  = *(const float4*)(sA1 + z * S1 + 64 + w4);
            float4 v4  = *(const float4*)(sA2 + z * S2 + w4);
            float4 z04 = *(const float4*)(sA2 + (64  + z) * S2 + w4);
            float4 z14 = *(const float4*)(sA2 + (128 + z) * S2 + w4);
            float4 z24 = *(const float4*)(sA2 + (192 + z) * S2 + w4);
            float4 at  = ((const float4*)sAttr)[z];

            float sv[4] = {s4.x, s4.y, s4.z, s4.w};
            float gv[4] = {g4.x, g4.y, g4.z, g4.w};
            float vv[4] = {v4.x, v4.y, v4.z, v4.w};
            float zz0[4] = {z04.x, z04.y, z04.z, z04.w};
            float zz1[4] = {z14.x, z14.y, z14.z, z14.w};
            float zz2[4] = {z24.x, z24.y, z24.z, z24.w};

            float silu4[4], r[12];
            #pragma unroll
            for (int i = 0; i < 4; i++) {
                const float s = ALPHA_C * sv[i];
                const float gg = ALPHA_C * gv[i];
                const float sig = 1.0f / (1.0f + __expf(-gg));
                silu4[i] = s / (1.0f + __expf(-s));
                const float c011v = C011_C * vv[i];
                const float c101a0 = C101_C * at.x;
                r[3*i+0] = sig * ALPHA_C * (c011v * at.y + c101a0 * zz0[i]);
                r[3*i+1] = sig * ALPHA_C * (c011v * at.z + c101a0 * zz1[i]);
                r[3*i+2] = sig * ALPHA_C * (c011v * at.w + c101a0 * zz2[i]);
            }

            float* ob = out + (size_t)zg * (4 * MUL);
            *(float4*)(ob + w4) = make_float4(silu4[0], silu4[1], silu4[2], silu4[3]);
            float* og = ob + 64 + 12 * grp;
            *(float4*)(og + 0) = make_float4(r[0], r[1], r[2],  r[3]);
            *(float4*)(og + 4) = make_float4(r[4], r[5], r[6],  r[7]);
            *(float4*)(og + 8) = make_float4(r[8], r[9], r[10], r[11]);
        }
    }
}

extern "C" void kernel_launch(void* const* d_in, const int* in_sizes, int n_in,
                              void* d_out, int out_size)
{
    const float* feats = (const float*)d_in[0];
    const float* attrs = (const float*)d_in[1];
    const float* W1 = (const float*)d_in[2];
    const float* W2 = (const float*)d_in[3];
    const float* W3 = (const float*)d_in[4];
    const float* W4 = (const float*)d_in[5];
    float* out = (float*)d_out;

    const int n = in_sizes[0] / (4 * MUL);
    const int ntiles = (n + NODE_TILE - 1) / NODE_TILE;

    cudaFuncSetAttribute(embedding_kernel,
                         cudaFuncAttributeMaxDynamicSharedMemorySize, SMEM_BYTES);

    int grid = GRID_CTAS < ntiles ? GRID_CTAS : ntiles;
    embedding_kernel<<<grid, THREADS, SMEM_BYTES>>>(feats, attrs, W1, W2, W3, W4,
                                                    out, n, ntiles);
}